// round 16
// baseline (speedup 1.0000x reference)
#include <cuda_runtime.h>
#include <math_constants.h>

#define BATCH 256
#define SEGMAX 8200
#define RROWS 4
#define TPB 256
#define WPB (TPB / 32)
#define SPG 32              // segments per group (phase 2)

__device__ int g_seg[3][SEGMAX];
__device__ int g_pbase[3];
__device__ int g_cend[3];
__device__ int g_cstart[3];
__device__ unsigned g_barcnt = 0;
__device__ unsigned g_bargen = 0;

// Sense-reversing grid barrier. ALL threads of ALL (co-resident) blocks must call.
__device__ __forceinline__ void grid_barrier() {
    __threadfence();
    __syncthreads();
    if (threadIdx.x == 0) {
        unsigned gen = atomicAdd(&g_bargen, 0u);
        if (atomicAdd(&g_barcnt, 1u) == (unsigned)gridDim.x - 1u) {
            atomicExch(&g_barcnt, 0u);
            __threadfence();
            atomicAdd(&g_bargen, 1u);   // release
        } else {
            while (atomicAdd(&g_bargen, 0u) == gen) { }   // acquire spin
        }
    }
    __syncthreads();
}

// Grouped reduction over 4 row-accumulators + 4 parallel parent updates
// (upper-level phases).
__device__ __forceinline__ void reduce_and_update(
    float acc[RROWS], int lane, int pnode,
    const float* srcBase, float* dstBase, int num_nodes) {
#pragma unroll
    for (int r = 0; r < RROWS; r++) {
        acc[r] += __shfl_xor_sync(0xffffffffu, acc[r], 16);
        acc[r] += __shfl_xor_sync(0xffffffffu, acc[r], 8);
    }
    int g = lane >> 3;
    float w = acc[0];
    w = (g == 1) ? acc[1] : w;
    w = (g == 2) ? acc[2] : w;
    w = (g == 3) ? acc[3] : w;
    w += __shfl_xor_sync(0xffffffffu, w, 4);
    w += __shfl_xor_sync(0xffffffffu, w, 2);
    w += __shfl_xor_sync(0xffffffffu, w, 1);
    if ((lane & 7) == 0) {
        float lse = __logf(w);
        const float* rowIn  = srcBase + (size_t)g * num_nodes;
        float*       rowOut = dstBase + (size_t)g * num_nodes;
        rowOut[pnode] = fmaxf(rowIn[pnode], lse);
    }
}

// Upper-level segment LSE (children read from out via __ldcg, cross-SM safe).
template <int SLOTS>
__device__ __forceinline__ void upper_seg(
    const float* __restrict__ in, float* __restrict__ out,
    int lvl, int i, int rg, int lane, int num_nodes) {
    const int* seg = g_seg[lvl];
    int cbase = seg[i];
    int n = seg[i + 1] - cbase;
    int pnode = g_pbase[lvl] + i;
    int cend = g_cend[lvl];

    size_t rowoff = (size_t)(rg * RROWS) * num_nodes;
    const float* srcBase = in + rowoff;
    float*       dstBase = out + rowoff;
    const float NEG_INF = -CUDART_INF_F;
    float acc[RROWS];

    if (n <= SLOTS * 32 && cbase + SLOTS * 32 <= cend) {
        float v[RROWS][SLOTS];
#pragma unroll
        for (int r = 0; r < RROWS; r++) {
            const float* src = dstBase + (size_t)r * num_nodes + cbase;
#pragma unroll
            for (int t = 0; t < SLOTS; t++) v[r][t] = __ldcg(src + lane + t * 32);
        }
#pragma unroll
        for (int r = 0; r < RROWS; r++) {
            acc[r] = 0.0f;
#pragma unroll
            for (int t = 0; t < SLOTS; t++) {
                float x = (lane + t * 32 < n) ? v[r][t] : NEG_INF;
                acc[r] += __expf(x);
            }
        }
    } else {
#pragma unroll
        for (int r = 0; r < RROWS; r++) acc[r] = 0.0f;
        for (int k = lane; k < n; k += 32)
#pragma unroll
            for (int r = 0; r < RROWS; r++)
                acc[r] += __expf(__ldcg(dstBase + (size_t)r * num_nodes + cbase + k));
    }
    reduce_and_update(acc, lane, pnode, srcBase, dstBase, num_nodes);
}

__global__ void __launch_bounds__(TPB, 8)
fused_kernel(const float* __restrict__ in, float* __restrict__ out,
             const int* __restrict__ f0, const int* __restrict__ M0,
             const int* __restrict__ c0, const int* __restrict__ p0, int N0, int P0,
             const int* __restrict__ f1, const int* __restrict__ M1,
             const int* __restrict__ c1, const int* __restrict__ p1, int N1, int P1,
             const int* __restrict__ f2, const int* __restrict__ M2,
             const int* __restrict__ c2, const int* __restrict__ p2, int N2, int P2,
             int num_nodes) {
    int lane = threadIdx.x & 31;
    int gw = blockIdx.x * WPB + (threadIdx.x >> 5);
    int nw = gridDim.x * WPB;
    int tid = blockIdx.x * TPB + threadIdx.x;
    int nthreads = gridDim.x * TPB;

    __shared__ int   sb[48];     // group segment boundaries (padded with +INF)
    __shared__ float ssum[SPG];  // per-segment exp sums

    // ---- Phase P: segment decode for all three levels ----
    {
        int Mv = M2[0];
        for (int k = tid; k < N2; k += nthreads) {
            int i = f2[k] / Mv;
            if (k == 0 || (f2[k - 1] / Mv) != i) g_seg[2][i] = c2[0] + k;
        }
        Mv = M1[0];
        for (int k = tid; k < N1; k += nthreads) {
            int i = f1[k] / Mv;
            if (k == 0 || (f1[k - 1] / Mv) != i) g_seg[1][i] = c1[0] + k;
        }
        Mv = M0[0];
        for (int k = tid; k < N0; k += nthreads) {
            int i = f0[k] / Mv;
            if (k == 0 || (f0[k - 1] / Mv) != i) g_seg[0][i] = c0[0] + k;
        }
        if (tid == 0) {
            g_seg[2][P2] = c2[0] + N2; g_pbase[2] = p2[0]; g_cend[2] = c2[0] + N2; g_cstart[2] = c2[0];
            g_seg[1][P1] = c1[0] + N1; g_pbase[1] = p1[0]; g_cend[1] = c1[0] + N1; g_cstart[1] = c1[0];
            g_seg[0][P0] = c0[0] + N0; g_pbase[0] = p0[0]; g_cend[0] = c0[0] + N0; g_cstart[0] = c0[0];
        }
    }
    grid_barrier();

    // ---- Phase 2 (leaves): streaming copy + segmented exp-sum ----
    // Block = (group of SPG consecutive segments, one batch row). The group's
    // leaves are one contiguous range -> aligned float4 stream (memcpy-shaped,
    // pipelinable). Segment attribution via smem boundary table; per-segment
    // sums via smem atomics; 32-thread parent update epilogue.
    {
        const int* seg = g_seg[2];
        int pbase = g_pbase[2];
        unsigned nn = (unsigned)num_nodes;
        unsigned totalElems = (unsigned)BATCH * nn;
        int ngroups = (P2 + SPG - 1) / SPG;
        int totalItems = ngroups * BATCH;

        for (int item = blockIdx.x; item < totalItems; item += gridDim.x) {
            int r = item / ngroups;          // slow dim: row
            int g = item - r * ngroups;      // fast dim: group (adjacent blocks share boundary lines)
            int segbase = g * SPG;
            int nsegs = min(SPG, P2 - segbase);

            if (threadIdx.x < 48) {
                int j = threadIdx.x;
                sb[j] = (j <= nsegs) ? seg[segbase + j] : 0x7FFFFFFF;
            }
            if (threadIdx.x < SPG) ssum[threadIdx.x] = 0.0f;
            __syncthreads();

            int base = sb[0];
            int end  = sb[nsegs];
            unsigned rowoff = (unsigned)r * nn;
            unsigned a = rowoff + (unsigned)base;
            int sh = (int)(a & 3u);
            unsigned awin = a - sh;              // 16B-aligned flat element index
            int Wq = (end - base + sh + 3) >> 2; // quads covering the window
            bool g0 = (g == 0);

            for (int q = threadIdx.x; q < Wq; q += TPB) {
                unsigned eidx = awin + 4u * q;
                int node0 = base - sh + 4 * q;
                float4 v;
                float* vp = (float*)&v;
                // Under-reach into level-2 parent region happens only for g==0
                // (race with parent updates) -> mask. OOB only at array end.
                bool vecOK = !(g0 && node0 < base) && (eidx + 3u < totalElems);
                if (vecOK) {
                    v = *(const float4*)(in + eidx);
                    *(float4*)(out + eidx) = v;
                } else {
#pragma unroll
                    for (int e = 0; e < 4; e++) {
                        unsigned ei = eidx + e;
                        int node = node0 + e;
                        bool ok = (ei < totalElems) && !(g0 && node < base);
                        vp[e] = ok ? in[ei] : 0.0f;
                        if (ok) out[ei] = vp[e];
                    }
                }
                // Segmented accumulation (only elements inside [base, end)).
                int nfirst = node0 < base ? base : node0;
                if (nfirst < end) {
                    int s = 0;
#pragma unroll
                    for (int st = 16; st; st >>= 1)
                        if (sb[s + st] <= nfirst) s += st;
                    float partial = 0.0f;
                    int curs = s;
#pragma unroll
                    for (int e = 0; e < 4; e++) {
                        int node = node0 + e;
                        if (node < base || node >= end) continue;
                        while (sb[s + 1] <= node) s++;
                        float ex = __expf(vp[e]);
                        if (s != curs) {
                            if (partial != 0.0f) atomicAdd(&ssum[curs], partial);
                            partial = ex;
                            curs = s;
                        } else {
                            partial += ex;
                        }
                    }
                    if (partial != 0.0f) atomicAdd(&ssum[curs], partial);
                }
            }
            __syncthreads();

            if (threadIdx.x < nsegs) {
                unsigned pidx = rowoff + (unsigned)(pbase + segbase + threadIdx.x);
                out[pidx] = fmaxf(in[pidx], __logf(ssum[threadIdx.x]));
            }
            __syncthreads();   // parent reads done before next iteration's re-init
        }
    }
    grid_barrier();

    // ---- Phase 1: level-1 parents (children = level-2 nodes, L2-hot) ----
    {
        int total = P1 << 6;
        for (int item = gw; item < total; item += nw)
            upper_seg<2>(in, out, 1, item >> 6, item & 63, lane, num_nodes);
    }
    grid_barrier();

    // ---- Phase 0: root ----
    {
        int total = P0 << 6;
        for (int item = gw; item < total; item += nw)
            upper_seg<4>(in, out, 0, item >> 6, item & 63, lane, num_nodes);
    }
}

extern "C" void kernel_launch(void* const* d_in, const int* in_sizes, int n_in,
                              void* d_out, int out_size) {
    // metadata order: scores, p0,f0,c0,P0,M0, p1,f1,c1,P1,M1, p2,f2,c2,P2,M2
    const float* scores = (const float*)d_in[0];
    const int* p0 = (const int*)d_in[1];
    const int* f0 = (const int*)d_in[2];
    const int* c0 = (const int*)d_in[3];
    const int* M0 = (const int*)d_in[5];
    const int* p1 = (const int*)d_in[6];
    const int* f1 = (const int*)d_in[7];
    const int* c1 = (const int*)d_in[8];
    const int* M1 = (const int*)d_in[10];
    const int* p2 = (const int*)d_in[11];
    const int* f2 = (const int*)d_in[12];
    const int* c2 = (const int*)d_in[13];
    const int* M2 = (const int*)d_in[15];

    int P0 = in_sizes[1],  N0 = in_sizes[2];
    int P1 = in_sizes[6],  N1 = in_sizes[7];
    int P2 = in_sizes[11], N2 = in_sizes[12];
    int num_nodes = in_sizes[0] / BATCH;
    float* out = (float*)d_out;

    // Size the persistent grid to guaranteed-co-resident blocks.
    int sms = 148, occ = 1;
    cudaDeviceGetAttribute(&sms, cudaDevAttrMultiProcessorCount, 0);
    cudaOccupancyMaxActiveBlocksPerMultiprocessor(&occ, fused_kernel, TPB, 0);
    if (occ < 1) occ = 1;
    if (occ > 8) occ = 8;
    int grid = sms * occ;

    fused_kernel<<<grid, TPB>>>(scores, out,
                                f0, M0, c0, p0, N0, P0,
                                f1, M1, c1, p1, N1, P1,
                                f2, M2, c2, p2, N2, P2,
                                num_nodes);
}

// round 17
// speedup vs baseline: 1.7961x; 1.7961x over previous
#include <cuda_runtime.h>
#include <math_constants.h>

#define BATCH 256
#define SEGMAX 8200
#define RROWS 4
#define TPB 256
#define WPB (TPB / 32)
#define CHUNK 4             // rowgroups per work unit in phase 2

__device__ int g_seg[3][SEGMAX];
__device__ int g_pbase[3];
__device__ int g_cend[3];
__device__ int g_cstart[3];
__device__ unsigned g_barcnt = 0;
__device__ unsigned g_bargen = 0;

// Sense-reversing grid barrier. ALL threads of ALL (co-resident) blocks must call.
__device__ __forceinline__ void grid_barrier() {
    __threadfence();
    __syncthreads();
    if (threadIdx.x == 0) {
        unsigned gen = atomicAdd(&g_bargen, 0u);
        if (atomicAdd(&g_barcnt, 1u) == (unsigned)gridDim.x - 1u) {
            atomicExch(&g_barcnt, 0u);
            __threadfence();
            atomicAdd(&g_bargen, 1u);   // release
        } else {
            while (atomicAdd(&g_bargen, 0u) == gen) { }   // acquire spin
        }
    }
    __syncthreads();
}

// Grouped reduction over 4 row-accumulators + 4 parallel parent updates
// (scalar fallback paths).
__device__ __forceinline__ void reduce_and_update(
    float acc[RROWS], int lane, int pnode,
    const float* srcBase, float* dstBase, int num_nodes) {
#pragma unroll
    for (int r = 0; r < RROWS; r++) {
        acc[r] += __shfl_xor_sync(0xffffffffu, acc[r], 16);
        acc[r] += __shfl_xor_sync(0xffffffffu, acc[r], 8);
    }
    int g = lane >> 3;
    float w = acc[0];
    w = (g == 1) ? acc[1] : w;
    w = (g == 2) ? acc[2] : w;
    w = (g == 3) ? acc[3] : w;
    w += __shfl_xor_sync(0xffffffffu, w, 4);
    w += __shfl_xor_sync(0xffffffffu, w, 2);
    w += __shfl_xor_sync(0xffffffffu, w, 1);
    if ((lane & 7) == 0) {
        float lse = __logf(w);
        const float* rowIn  = srcBase + (size_t)g * num_nodes;
        float*       rowOut = dstBase + (size_t)g * num_nodes;
        rowOut[pnode] = fmaxf(rowIn[pnode], lse);
    }
}

// Upper-level segment LSE (children read from out via __ldcg, cross-SM safe).
template <int SLOTS>
__device__ __forceinline__ void upper_seg(
    const float* __restrict__ in, float* __restrict__ out,
    int lvl, int i, int rg, int lane, int num_nodes) {
    const int* seg = g_seg[lvl];
    int cbase = seg[i];
    int n = seg[i + 1] - cbase;
    int pnode = g_pbase[lvl] + i;
    int cend = g_cend[lvl];

    size_t rowoff = (size_t)(rg * RROWS) * num_nodes;
    const float* srcBase = in + rowoff;
    float*       dstBase = out + rowoff;
    const float NEG_INF = -CUDART_INF_F;
    float acc[RROWS];

    if (n <= SLOTS * 32 && cbase + SLOTS * 32 <= cend) {
        float v[RROWS][SLOTS];
#pragma unroll
        for (int r = 0; r < RROWS; r++) {
            const float* src = dstBase + (size_t)r * num_nodes + cbase;
#pragma unroll
            for (int t = 0; t < SLOTS; t++) v[r][t] = __ldcg(src + lane + t * 32);
        }
#pragma unroll
        for (int r = 0; r < RROWS; r++) {
            acc[r] = 0.0f;
#pragma unroll
            for (int t = 0; t < SLOTS; t++) {
                float x = (lane + t * 32 < n) ? v[r][t] : NEG_INF;
                acc[r] += __expf(x);
            }
        }
    } else {
#pragma unroll
        for (int r = 0; r < RROWS; r++) acc[r] = 0.0f;
        for (int k = lane; k < n; k += 32)
#pragma unroll
            for (int r = 0; r < RROWS; r++)
                acc[r] += __expf(__ldcg(dstBase + (size_t)r * num_nodes + cbase + k));
    }
    reduce_and_update(acc, lane, pnode, srcBase, dstBase, num_nodes);
}

__global__ void __launch_bounds__(TPB)
fused_kernel(const float* __restrict__ in, float* __restrict__ out,
             const int* __restrict__ f0, const int* __restrict__ M0,
             const int* __restrict__ c0, const int* __restrict__ p0, int N0, int P0,
             const int* __restrict__ f1, const int* __restrict__ M1,
             const int* __restrict__ c1, const int* __restrict__ p1, int N1, int P1,
             const int* __restrict__ f2, const int* __restrict__ M2,
             const int* __restrict__ c2, const int* __restrict__ p2, int N2, int P2,
             int num_nodes) {
    int lane = threadIdx.x & 31;
    int gw = blockIdx.x * WPB + (threadIdx.x >> 5);
    int nw = gridDim.x * WPB;
    int tid = blockIdx.x * TPB + threadIdx.x;
    int nthreads = gridDim.x * TPB;

    // ---- Phase P: segment decode for all three levels ----
    {
        int Mv = M2[0];
        for (int k = tid; k < N2; k += nthreads) {
            int i = f2[k] / Mv;
            if (k == 0 || (f2[k - 1] / Mv) != i) g_seg[2][i] = c2[0] + k;
        }
        Mv = M1[0];
        for (int k = tid; k < N1; k += nthreads) {
            int i = f1[k] / Mv;
            if (k == 0 || (f1[k - 1] / Mv) != i) g_seg[1][i] = c1[0] + k;
        }
        Mv = M0[0];
        for (int k = tid; k < N0; k += nthreads) {
            int i = f0[k] / Mv;
            if (k == 0 || (f0[k - 1] / Mv) != i) g_seg[0][i] = c0[0] + k;
        }
        if (tid == 0) {
            g_seg[2][P2] = c2[0] + N2; g_pbase[2] = p2[0]; g_cend[2] = c2[0] + N2; g_cstart[2] = c2[0];
            g_seg[1][P1] = c1[0] + N1; g_pbase[1] = p1[0]; g_cend[1] = c1[0] + N1; g_cstart[1] = c1[0];
            g_seg[0][P0] = c0[0] + N0; g_pbase[0] = p0[0]; g_cend[0] = c0[0] + N0; g_cstart[0] = c0[0];
        }
    }
    grid_barrier();

    // ---- Phase 2 (leaves): fused copy in->out + LSE into level-2 parents ----
    // Work unit = (segment i, chunk of CHUNK rowgroups): one seg lookup + one
    // guard per unit, inner loop over rowgroups with independent iterations
    // (compiler-pipelinable). Per-(i,rg) body identical to the R15 version.
    {
        const int* seg = g_seg[2];
        int pbase = g_pbase[2];
        int leafStart = g_cstart[2];
        int leafEnd = g_cend[2];
        const float NEG_INF = -CUDART_INF_F;
        unsigned nn = (unsigned)num_nodes;
        int half = lane >> 4;
        int q = (lane & 15) << 2;
        const int CPG = 64 / CHUNK;              // chunks per segment
        int nunits = P2 * CPG;
        for (int u = gw; u < nunits; u += nw) {
            int i = u / CPG;
            int c = u - i * CPG;
            int cbase = seg[i];
            int n = seg[i + 1] - cbase;
            int pnode = pbase + i;
            int rg0 = c * CHUNK;

            if (n <= 61 && cbase >= leafStart + 4 && cbase + 64 <= leafEnd) {
                // === Vectorized fast path, CHUNK independent rowgroups ===
#pragma unroll 2
                for (int rg = rg0; rg < rg0 + CHUNK; rg++) {
                    unsigned rowA = (unsigned)(rg * RROWS + half) * nn;
                    unsigned rowB = rowA + 2u * nn;
                    unsigned fA = rowA + (unsigned)cbase;
                    unsigned fB = rowB + (unsigned)cbase;
                    int shA = (int)(fA & 3u);
                    int shB = (int)(fB & 3u);
                    unsigned eA = fA - shA + q;
                    unsigned eB = fB - shB + q;

                    float4 vA = *(const float4*)(in + eA);
                    float4 vB = *(const float4*)(in + eB);
                    *(float4*)(out + eA) = vA;
                    *(float4*)(out + eB) = vB;

                    float accA = 0.0f, accB = 0.0f;
                    {
                        float xs[4] = {vA.x, vA.y, vA.z, vA.w};
#pragma unroll
                        for (int e = 0; e < 4; e++) {
                            bool ok = (unsigned)(q + e - shA) < (unsigned)n;
                            accA += __expf(ok ? xs[e] : NEG_INF);
                        }
                    }
                    {
                        float xs[4] = {vB.x, vB.y, vB.z, vB.w};
#pragma unroll
                        for (int e = 0; e < 4; e++) {
                            bool ok = (unsigned)(q + e - shB) < (unsigned)n;
                            accB += __expf(ok ? xs[e] : NEG_INF);
                        }
                    }
#pragma unroll
                    for (int o = 1; o <= 8; o <<= 1) {
                        accA += __shfl_xor_sync(0xffffffffu, accA, o);
                        accB += __shfl_xor_sync(0xffffffffu, accB, o);
                    }
                    if ((lane & 15) == 0) {
                        unsigned pA = rowA + (unsigned)pnode;
                        unsigned pB = rowB + (unsigned)pnode;
                        out[pA] = fmaxf(in[pA], __logf(accA));
                        out[pB] = fmaxf(in[pB], __logf(accB));
                    }
                }
            } else {
                // === Scalar predicated path (edge segments / n>61) ===
                for (int rg = rg0; rg < rg0 + CHUNK; rg++) {
                    size_t rowoff = (size_t)(rg * RROWS) * num_nodes;
                    const float* srcBase = in + rowoff;
                    float*       dstBase = out + rowoff;
                    float acc[RROWS];
                    if (n <= 64) {
                        float v[RROWS][2];
#pragma unroll
                        for (int r = 0; r < RROWS; r++) {
                            const float* src = srcBase + (size_t)r * num_nodes;
                            v[r][0] = (lane < n)      ? src[cbase + lane]      : NEG_INF;
                            v[r][1] = (lane + 32 < n) ? src[cbase + lane + 32] : NEG_INF;
                        }
#pragma unroll
                        for (int r = 0; r < RROWS; r++) {
                            float* dst = dstBase + (size_t)r * num_nodes;
                            if (lane < n)      dst[cbase + lane]      = v[r][0];
                            if (lane + 32 < n) dst[cbase + lane + 32] = v[r][1];
                        }
#pragma unroll
                        for (int r = 0; r < RROWS; r++)
                            acc[r] = __expf(v[r][0]) + __expf(v[r][1]);
                    } else {
#pragma unroll
                        for (int r = 0; r < RROWS; r++) acc[r] = 0.0f;
                        for (int k = lane; k < n; k += 32) {
#pragma unroll
                            for (int r = 0; r < RROWS; r++) {
                                float x = srcBase[(size_t)r * num_nodes + cbase + k];
                                dstBase[(size_t)r * num_nodes + cbase + k] = x;
                                acc[r] += __expf(x);
                            }
                        }
                    }
                    reduce_and_update(acc, lane, pnode, srcBase, dstBase, num_nodes);
                }
            }
        }
    }
    grid_barrier();

    // ---- Phase 1: level-1 parents (children = level-2 nodes, L2-hot) ----
    {
        int total = P1 << 6;
        for (int item = gw; item < total; item += nw)
            upper_seg<2>(in, out, 1, item >> 6, item & 63, lane, num_nodes);
    }
    grid_barrier();

    // ---- Phase 0: root ----
    {
        int total = P0 << 6;
        for (int item = gw; item < total; item += nw)
            upper_seg<4>(in, out, 0, item >> 6, item & 63, lane, num_nodes);
    }
}

extern "C" void kernel_launch(void* const* d_in, const int* in_sizes, int n_in,
                              void* d_out, int out_size) {
    // metadata order: scores, p0,f0,c0,P0,M0, p1,f1,c1,P1,M1, p2,f2,c2,P2,M2
    const float* scores = (const float*)d_in[0];
    const int* p0 = (const int*)d_in[1];
    const int* f0 = (const int*)d_in[2];
    const int* c0 = (const int*)d_in[3];
    const int* M0 = (const int*)d_in[5];
    const int* p1 = (const int*)d_in[6];
    const int* f1 = (const int*)d_in[7];
    const int* c1 = (const int*)d_in[8];
    const int* M1 = (const int*)d_in[10];
    const int* p2 = (const int*)d_in[11];
    const int* f2 = (const int*)d_in[12];
    const int* c2 = (const int*)d_in[13];
    const int* M2 = (const int*)d_in[15];

    int P0 = in_sizes[1],  N0 = in_sizes[2];
    int P1 = in_sizes[6],  N1 = in_sizes[7];
    int P2 = in_sizes[11], N2 = in_sizes[12];
    int num_nodes = in_sizes[0] / BATCH;
    float* out = (float*)d_out;

    // Size the persistent grid to guaranteed-co-resident blocks.
    int sms = 148, occ = 1;
    cudaDeviceGetAttribute(&sms, cudaDevAttrMultiProcessorCount, 0);
    cudaOccupancyMaxActiveBlocksPerMultiprocessor(&occ, fused_kernel, TPB, 0);
    if (occ < 1) occ = 1;
    if (occ > 8) occ = 8;
    int grid = sms * occ;

    fused_kernel<<<grid, TPB>>>(scores, out,
                                f0, M0, c0, p0, N0, P0,
                                f1, M1, c1, p1, N1, P1,
                                f2, M2, c2, p2, N2, P2,
                                num_nodes);
}